// round 2
// baseline (speedup 1.0000x reference)
#include <cuda_runtime.h>
#include <math.h>

#define TOK   2048
#define BATCH 8
#define NEMBD 768
#define HS    64
#define MROWS (BATCH*TOK)          // 16384

// ---------------- scratch (device globals; no allocation allowed) ----------
static __device__ float g_q[MROWS*HS];
static __device__ float g_k[MROWS*HS];
static __device__ float g_v[MROWS*HS];

// split-K partials: unit = ((b*16 + qb)*4 + chunk), 512 units x 128 rows
static __device__ float g_part_o[512*128*HS];
static __device__ float g_part_m[512*128];
static __device__ float g_part_l[512*128];

// ---------------- QKV projection: out[M,64] = x[M,768] @ W[768,64] ---------
__global__ __launch_bounds__(256) void qkv_gemm(const float* __restrict__ x,
                                                const float* __restrict__ Wk,
                                                const float* __restrict__ Wq,
                                                const float* __restrict__ Wv) {
    __shared__ float As[32][64];   // As[k][m]  (A transposed in smem)
    __shared__ float Bs[32][64];   // Bs[k][n]

    const float* W;
    float* out;
    if (blockIdx.y == 0)      { W = Wq; out = g_q; }
    else if (blockIdx.y == 1) { W = Wk; out = g_k; }
    else                      { W = Wv; out = g_v; }

    const int tid = threadIdx.x;
    const int tx  = tid & 15;          // 0..15 -> 4 output cols
    const int ty  = tid >> 4;          // 0..15 -> 4 output rows
    const int row0 = blockIdx.x * 64;

    float acc[4][4];
#pragma unroll
    for (int i = 0; i < 4; i++)
#pragma unroll
        for (int j = 0; j < 4; j++) acc[i][j] = 0.f;

    for (int k0 = 0; k0 < NEMBD; k0 += 32) {
        // load A tile 64x32 (transposed into As[k][m]) : 256 threads x 2 float4
        {
            const int r  = tid >> 3;           // 0..31
            const int c4 = (tid & 7) * 4;      // 0..28
#pragma unroll
            for (int half = 0; half < 2; half++) {
                const int row = r + half * 32;
                float4 a = *(const float4*)&x[(size_t)(row0 + row) * NEMBD + k0 + c4];
                As[c4 + 0][row] = a.x;
                As[c4 + 1][row] = a.y;
                As[c4 + 2][row] = a.z;
                As[c4 + 3][row] = a.w;
            }
        }
        // load B tile 32x64 : 256 threads x 2 float4
        {
            const int kr = tid >> 4;           // 0..15
            const int c4 = (tid & 15) * 4;
            *(float4*)&Bs[kr][c4]      = *(const float4*)&W[(size_t)(k0 + kr) * HS + c4];
            *(float4*)&Bs[kr + 16][c4] = *(const float4*)&W[(size_t)(k0 + kr + 16) * HS + c4];
        }
        __syncthreads();
#pragma unroll
        for (int kk = 0; kk < 32; kk++) {
            float4 a4 = *(const float4*)&As[kk][ty * 4];
            float4 b4 = *(const float4*)&Bs[kk][tx * 4];
            float av[4] = {a4.x, a4.y, a4.z, a4.w};
            float bv[4] = {b4.x, b4.y, b4.z, b4.w};
#pragma unroll
            for (int i = 0; i < 4; i++)
#pragma unroll
                for (int j = 0; j < 4; j++) acc[i][j] += av[i] * bv[j];
        }
        __syncthreads();
    }
#pragma unroll
    for (int i = 0; i < 4; i++) {
        float4 r = make_float4(acc[i][0], acc[i][1], acc[i][2], acc[i][3]);
        *(float4*)&out[(size_t)(row0 + ty * 4 + i) * HS + tx * 4] = r;
    }
}

// ---------------- flash attention partial (split along keys) ---------------
// grid = (4 chunks, 16 qblocks, 8 batches), 128 threads (one query row each)
__global__ __launch_bounds__(128) void attn_partial() {
    __shared__ float Ksh[64][64];
    __shared__ float Vsh[64][64];

    const int chunk = blockIdx.x;
    const int qb    = blockIdx.y;
    const int b     = blockIdx.z;

    const int nkb = 2 * (qb + 1);          // key tiles of 64 for this q block
    const int kb0 = chunk * 8;
    if (kb0 >= nkb) return;                // inactive split unit
    const int kb1 = (kb0 + 8 < nkb) ? kb0 + 8 : nkb;

    const int tid  = threadIdx.x;
    const int qrow = qb * 128 + tid;       // within-batch query index

    const float* qptr = g_q + ((size_t)(b * TOK + qrow)) * HS;
    float4 q[16];
#pragma unroll
    for (int i = 0; i < 16; i++) {
        float4 t = *(const float4*)&qptr[i * 4];
        q[i] = make_float4(t.x * 0.125f, t.y * 0.125f, t.z * 0.125f, t.w * 0.125f);
    }

    float4 o[16];
#pragma unroll
    for (int i = 0; i < 16; i++) o[i] = make_float4(0.f, 0.f, 0.f, 0.f);
    float m = -INFINITY;
    float l = 0.f;

    for (int kb = kb0; kb < kb1; kb++) {
        const float* kptr = g_k + ((size_t)(b * TOK + kb * 64)) * HS;
        const float* vptr = g_v + ((size_t)(b * TOK + kb * 64)) * HS;
#pragma unroll
        for (int i = 0; i < 8; i++) {
            int idx = tid + i * 128;               // 0..1023 float4 slots
            int r = idx >> 4;
            int c = (idx & 15) * 4;
            *(float4*)&Ksh[r][c] = *(const float4*)&kptr[r * HS + c];
            *(float4*)&Vsh[r][c] = *(const float4*)&vptr[r * HS + c];
        }
        __syncthreads();

        const int kbase = kb * 64;
#pragma unroll 1
        for (int ch = 0; ch < 4; ch++) {
            float s[16];
#pragma unroll
            for (int jj = 0; jj < 16; jj++) {
                const int j = ch * 16 + jj;
                const float4* kr = (const float4*)Ksh[j];
                float a0 = 0.f, a1 = 0.f, a2 = 0.f, a3 = 0.f;
#pragma unroll
                for (int h = 0; h < 16; h += 4) {
                    float4 k0 = kr[h + 0], k1 = kr[h + 1], k2 = kr[h + 2], k3 = kr[h + 3];
                    a0 += q[h + 0].x * k0.x + q[h + 0].y * k0.y + q[h + 0].z * k0.z + q[h + 0].w * k0.w;
                    a1 += q[h + 1].x * k1.x + q[h + 1].y * k1.y + q[h + 1].z * k1.z + q[h + 1].w * k1.w;
                    a2 += q[h + 2].x * k2.x + q[h + 2].y * k2.y + q[h + 2].z * k2.z + q[h + 2].w * k2.w;
                    a3 += q[h + 3].x * k3.x + q[h + 3].y * k3.y + q[h + 3].z * k3.z + q[h + 3].w * k3.w;
                }
                float sv = (a0 + a1) + (a2 + a3);
                s[jj] = (kbase + j <= qrow) ? sv : -INFINITY;
            }
            float cmax = s[0];
#pragma unroll
            for (int jj = 1; jj < 16; jj++) cmax = fmaxf(cmax, s[jj]);
            const float mnew  = fmaxf(m, cmax);
            const float alpha = __expf(m - mnew);   // m=-inf first time -> 0
            float psum = 0.f;
#pragma unroll
            for (int jj = 0; jj < 16; jj++) {
                s[jj] = __expf(s[jj] - mnew);       // masked -> exp(-inf)=0
                psum += s[jj];
            }
            l = l * alpha + psum;
            m = mnew;
#pragma unroll
            for (int i = 0; i < 16; i++) {
                o[i].x *= alpha; o[i].y *= alpha; o[i].z *= alpha; o[i].w *= alpha;
            }
#pragma unroll
            for (int jj = 0; jj < 16; jj++) {
                const float4* vr = (const float4*)Vsh[ch * 16 + jj];
                const float p = s[jj];
#pragma unroll
                for (int i = 0; i < 16; i++) {
                    float4 vv = vr[i];
                    o[i].x += p * vv.x; o[i].y += p * vv.y;
                    o[i].z += p * vv.z; o[i].w += p * vv.w;
                }
            }
        }
        __syncthreads();
    }

    const int unit = (b * 16 + qb) * 4 + chunk;
    g_part_m[unit * 128 + tid] = m;
    g_part_l[unit * 128 + tid] = l;
    float* po = g_part_o + ((size_t)(unit * 128 + tid)) * HS;
#pragma unroll
    for (int i = 0; i < 16; i++) *(float4*)&po[i * 4] = o[i];
}

// ---------------- combine split-K partials ---------------------------------
__global__ __launch_bounds__(128) void attn_combine(float* __restrict__ out) {
    const int row = blockIdx.x * 128 + threadIdx.x;   // 0..16383 (b*2048+t)
    const int b = row >> 11;
    const int t = row & 2047;
    const int qb = t >> 7;
    const int lane = t & 127;
    const int nkb = 2 * (qb + 1);
    const int nchunk = (nkb + 7) / 8;                 // 1..4 active chunks
    const int base_unit = (b * 16 + qb) * 4;

    float M = -INFINITY;
    for (int c = 0; c < nchunk; c++)
        M = fmaxf(M, g_part_m[(base_unit + c) * 128 + lane]);

    float w[4];
    float L = 0.f;
    for (int c = 0; c < nchunk; c++) {
        float wm = __expf(g_part_m[(base_unit + c) * 128 + lane] - M);
        w[c] = wm;
        L += wm * g_part_l[(base_unit + c) * 128 + lane];
    }
    const float inv = 1.f / L;

    float* op = out + (size_t)row * HS;
#pragma unroll
    for (int i = 0; i < 16; i++) {
        float4 acc = make_float4(0.f, 0.f, 0.f, 0.f);
        for (int c = 0; c < nchunk; c++) {
            const float* po = g_part_o + ((size_t)((base_unit + c) * 128 + lane)) * HS;
            float4 v = *(const float4*)&po[i * 4];
            acc.x += w[c] * v.x; acc.y += w[c] * v.y;
            acc.z += w[c] * v.z; acc.w += w[c] * v.w;
        }
        acc.x *= inv; acc.y *= inv; acc.z *= inv; acc.w *= inv;
        *(float4*)&op[i * 4] = acc;
    }
}

// ---------------- launch ----------------------------------------------------
extern "C" void kernel_launch(void* const* d_in, const int* in_sizes, int n_in,
                              void* d_out, int out_size) {
    const float* x  = (const float*)d_in[0];
    const float* Wk = (const float*)d_in[1];
    const float* Wq = (const float*)d_in[2];
    const float* Wv = (const float*)d_in[3];
    float* out = (float*)d_out;

    qkv_gemm<<<dim3(MROWS / 64, 3), 256>>>(x, Wk, Wq, Wv);
    attn_partial<<<dim3(4, 16, BATCH), 128>>>();
    attn_combine<<<dim3(MROWS / 128), 128>>>(out);
}

// round 4
// speedup vs baseline: 3.2028x; 3.2028x over previous
#include <cuda_runtime.h>
#include <math.h>
#include <stdint.h>

#define TOK   2048
#define BATCH 8
#define NEMBD 768
#define HS    64
#define MROWS (BATCH*TOK)          // 16384

// ---------------- scratch (device globals; no allocation allowed) ----------
static __device__ float g_q[MROWS*HS];
static __device__ float g_k[MROWS*HS];
static __device__ float g_v[MROWS*HS];

// split-K partials: unit = ((b*32 + qb)*4 + chunk), 1024 units x 64 rows
static __device__ float g_part_o[1024*64*HS];
static __device__ float g_part_m[1024*64];
static __device__ float g_part_l[1024*64];

// ---------------- tf32 helpers ---------------------------------------------
__device__ __forceinline__ uint32_t f2tf32(float f) {
    uint32_t u;
    asm("cvt.rna.tf32.f32 %0, %1;" : "=r"(u) : "f"(f));
    return u;
}

__device__ __forceinline__ void mma_tf32(float c[4],
                                         uint32_t a0, uint32_t a1, uint32_t a2, uint32_t a3,
                                         uint32_t b0, uint32_t b1) {
    asm volatile(
        "mma.sync.aligned.m16n8k8.row.col.f32.tf32.tf32.f32 "
        "{%0,%1,%2,%3},{%4,%5,%6,%7},{%8,%9},{%0,%1,%2,%3};"
        : "+f"(c[0]), "+f"(c[1]), "+f"(c[2]), "+f"(c[3])
        : "r"(a0), "r"(a1), "r"(a2), "r"(a3), "r"(b0), "r"(b1));
}

// ---------------- QKV projection: out[M,64] = x[M,768] @ W[768,64] ---------
// block = 128 threads (4 warps), tile 128 rows x 64 cols, BK = 32
#define AST 40   // As stride (words): bank = g*8 + tig -> conflict-free frags
#define BST 72   // Bs stride (words): bank = tig*8 + g -> conflict-free frags
__global__ __launch_bounds__(128) void qkv_gemm_tc(const float* __restrict__ x,
                                                   const float* __restrict__ Wk,
                                                   const float* __restrict__ Wq,
                                                   const float* __restrict__ Wv) {
    __shared__ uint32_t As[128 * AST];
    __shared__ uint32_t Bs[32 * BST];

    const float* W;
    float* out;
    if (blockIdx.y == 0)      { W = Wq; out = g_q; }
    else if (blockIdx.y == 1) { W = Wk; out = g_k; }
    else                      { W = Wv; out = g_v; }

    const int tid  = threadIdx.x;
    const int warp = tid >> 5;
    const int lane = tid & 31;
    const int g    = lane >> 2;
    const int tig  = lane & 3;
    const int row0 = blockIdx.x * 128;

    float acc[2][8][4];
#pragma unroll
    for (int mt = 0; mt < 2; mt++)
#pragma unroll
        for (int nt = 0; nt < 8; nt++)
#pragma unroll
            for (int i = 0; i < 4; i++) acc[mt][nt][i] = 0.f;

    for (int k0 = 0; k0 < NEMBD; k0 += 32) {
        // A tile 128x32 (coalesced: 8 lanes per row)
#pragma unroll
        for (int i = 0; i < 8; i++) {
            int idx = tid + i * 128;           // 0..1023 float4 slots
            int r   = idx >> 3;
            int c4  = (idx & 7) * 4;
            float4 a = *(const float4*)&x[(size_t)(row0 + r) * NEMBD + k0 + c4];
            uint4 t = make_uint4(f2tf32(a.x), f2tf32(a.y), f2tf32(a.z), f2tf32(a.w));
            *(uint4*)&As[r * AST + c4] = t;
        }
        // B tile 32x64
#pragma unroll
        for (int i = 0; i < 4; i++) {
            int idx = tid + i * 128;           // 0..511 float4 slots
            int r   = idx >> 4;
            int c4  = (idx & 15) * 4;
            float4 b = *(const float4*)&W[(size_t)(k0 + r) * HS + c4];
            uint4 t = make_uint4(f2tf32(b.x), f2tf32(b.y), f2tf32(b.z), f2tf32(b.w));
            *(uint4*)&Bs[r * BST + c4] = t;
        }
        __syncthreads();

#pragma unroll
        for (int kk = 0; kk < 4; kk++) {
            uint32_t af[2][4];
#pragma unroll
            for (int mt = 0; mt < 2; mt++) {
                const int m0 = warp * 32 + mt * 16;
                af[mt][0] = As[(m0 + g) * AST + kk * 8 + tig];
                af[mt][1] = As[(m0 + g + 8) * AST + kk * 8 + tig];
                af[mt][2] = As[(m0 + g) * AST + kk * 8 + tig + 4];
                af[mt][3] = As[(m0 + g + 8) * AST + kk * 8 + tig + 4];
            }
#pragma unroll
            for (int nt = 0; nt < 8; nt++) {
                uint32_t b0 = Bs[(kk * 8 + tig) * BST + nt * 8 + g];
                uint32_t b1 = Bs[(kk * 8 + tig + 4) * BST + nt * 8 + g];
                mma_tf32(acc[0][nt], af[0][0], af[0][1], af[0][2], af[0][3], b0, b1);
                mma_tf32(acc[1][nt], af[1][0], af[1][1], af[1][2], af[1][3], b0, b1);
            }
        }
        __syncthreads();
    }

#pragma unroll
    for (int mt = 0; mt < 2; mt++) {
        const int r0 = row0 + warp * 32 + mt * 16 + g;
#pragma unroll
        for (int nt = 0; nt < 8; nt++) {
            const int c = nt * 8 + 2 * tig;
            *(float2*)&out[(size_t)r0 * HS + c]       = make_float2(acc[mt][nt][0], acc[mt][nt][1]);
            *(float2*)&out[(size_t)(r0 + 8) * HS + c] = make_float2(acc[mt][nt][2], acc[mt][nt][3]);
        }
    }
}

// ---------------- flash attention partial (tensor cores, split along keys) --
// grid = (4 chunks, 32 qblocks, 8 batches), 128 threads (4 warps)
// block handles 64 q rows; warp w handles rows w*16 .. w*16+15
#define KST 72   // stride (words) for K/V/Q/P tiles
__global__ __launch_bounds__(128) void attn_partial_tc() {
    __shared__ uint32_t Ksh[64 * KST];   // K tile, then reused for P tile
    __shared__ uint32_t Vsh[64 * KST];   // Q staging, then V tile

    const int chunk = blockIdx.x;
    const int qb    = blockIdx.y;        // 0..31, 64 rows each
    const int b     = blockIdx.z;

    const int nkb = qb + 1;              // 64-key tiles needed (causal)
    const int kb0 = chunk * 8;
    if (kb0 >= nkb) return;
    const int kb1 = (kb0 + 8 < nkb) ? kb0 + 8 : nkb;

    const int tid  = threadIdx.x;
    const int warp = tid >> 5;
    const int lane = tid & 31;
    const int g    = lane >> 2;
    const int tig  = lane & 3;
    const int qrow0 = qb * 64;           // block's first q row (within batch)

    // ---- stage Q (scaled, tf32) through Vsh, then pull fragments -----------
#pragma unroll
    for (int i = 0; i < 8; i++) {
        int idx = tid + i * 128;
        int r   = idx >> 4;
        int c4  = (idx & 15) * 4;
        float4 q = *(const float4*)&g_q[((size_t)(b * TOK + qrow0 + r)) * HS + c4];
        uint4 t = make_uint4(f2tf32(q.x * 0.125f), f2tf32(q.y * 0.125f),
                             f2tf32(q.z * 0.125f), f2tf32(q.w * 0.125f));
        *(uint4*)&Vsh[r * KST + c4] = t;
    }
    __syncthreads();

    uint32_t qf[8][4];
    const int mrow = warp * 16;          // warp's first local row
#pragma unroll
    for (int ks = 0; ks < 8; ks++) {
        qf[ks][0] = Vsh[(mrow + g) * KST + ks * 8 + tig];
        qf[ks][1] = Vsh[(mrow + g + 8) * KST + ks * 8 + tig];
        qf[ks][2] = Vsh[(mrow + g) * KST + ks * 8 + tig + 4];
        qf[ks][3] = Vsh[(mrow + g + 8) * KST + ks * 8 + tig + 4];
    }
    __syncthreads();

    float oacc[8][4];
#pragma unroll
    for (int nt = 0; nt < 8; nt++)
#pragma unroll
        for (int i = 0; i < 4; i++) oacc[nt][i] = 0.f;

    float m0r = -INFINITY, m1r = -INFINITY;   // rows g and g+8
    float l0 = 0.f, l1 = 0.f;

    const int rg0 = qrow0 + mrow + g;         // global (in-batch) q rows
    const int rg1 = rg0 + 8;

    for (int kb = kb0; kb < kb1; kb++) {
        // ---- load K and V tiles (tf32) ------------------------------------
#pragma unroll
        for (int i = 0; i < 8; i++) {
            int idx = tid + i * 128;
            int r   = idx >> 4;
            int c4  = (idx & 15) * 4;
            size_t base = ((size_t)(b * TOK + kb * 64 + r)) * HS + c4;
            float4 kv = *(const float4*)&g_k[base];
            float4 vv = *(const float4*)&g_v[base];
            *(uint4*)&Ksh[r * KST + c4] = make_uint4(f2tf32(kv.x), f2tf32(kv.y), f2tf32(kv.z), f2tf32(kv.w));
            *(uint4*)&Vsh[r * KST + c4] = make_uint4(f2tf32(vv.x), f2tf32(vv.y), f2tf32(vv.z), f2tf32(vv.w));
        }
        __syncthreads();

        // ---- S = Q K^T (16 x 64 per warp) ---------------------------------
        float sacc[8][4];
#pragma unroll
        for (int nt = 0; nt < 8; nt++) {
#pragma unroll
            for (int i = 0; i < 4; i++) sacc[nt][i] = 0.f;
#pragma unroll
            for (int ks = 0; ks < 8; ks++) {
                uint32_t b0 = Ksh[(nt * 8 + g) * KST + ks * 8 + tig];
                uint32_t b1 = Ksh[(nt * 8 + g) * KST + ks * 8 + tig + 4];
                mma_tf32(sacc[nt], qf[ks][0], qf[ks][1], qf[ks][2], qf[ks][3], b0, b1);
            }
        }

        // ---- causal mask (only the diagonal tile can clip) ----------------
        if (kb == qb) {
            const int colbase = kb * 64;
#pragma unroll
            for (int nt = 0; nt < 8; nt++) {
                const int c0 = colbase + nt * 8 + 2 * tig;
                if (c0 > rg0)     sacc[nt][0] = -INFINITY;
                if (c0 + 1 > rg0) sacc[nt][1] = -INFINITY;
                if (c0 > rg1)     sacc[nt][2] = -INFINITY;
                if (c0 + 1 > rg1) sacc[nt][3] = -INFINITY;
            }
        }

        // ---- online softmax -----------------------------------------------
        float mx0 = -INFINITY, mx1 = -INFINITY;
#pragma unroll
        for (int nt = 0; nt < 8; nt++) {
            mx0 = fmaxf(mx0, fmaxf(sacc[nt][0], sacc[nt][1]));
            mx1 = fmaxf(mx1, fmaxf(sacc[nt][2], sacc[nt][3]));
        }
        mx0 = fmaxf(mx0, __shfl_xor_sync(0xffffffffu, mx0, 1));
        mx0 = fmaxf(mx0, __shfl_xor_sync(0xffffffffu, mx0, 2));
        mx1 = fmaxf(mx1, __shfl_xor_sync(0xffffffffu, mx1, 1));
        mx1 = fmaxf(mx1, __shfl_xor_sync(0xffffffffu, mx1, 2));

        const float mn0 = fmaxf(m0r, mx0);
        const float mn1 = fmaxf(m1r, mx1);
        const float alpha0 = __expf(m0r - mn0);   // first iter: exp(-inf)=0
        const float alpha1 = __expf(m1r - mn1);
        m0r = mn0; m1r = mn1;

        float ps0 = 0.f, ps1 = 0.f;
#pragma unroll
        for (int nt = 0; nt < 8; nt++) {
            sacc[nt][0] = __expf(sacc[nt][0] - mn0);
            sacc[nt][1] = __expf(sacc[nt][1] - mn0);
            sacc[nt][2] = __expf(sacc[nt][2] - mn1);
            sacc[nt][3] = __expf(sacc[nt][3] - mn1);
            ps0 += sacc[nt][0] + sacc[nt][1];
            ps1 += sacc[nt][2] + sacc[nt][3];
        }
        ps0 += __shfl_xor_sync(0xffffffffu, ps0, 1);
        ps0 += __shfl_xor_sync(0xffffffffu, ps0, 2);
        ps1 += __shfl_xor_sync(0xffffffffu, ps1, 1);
        ps1 += __shfl_xor_sync(0xffffffffu, ps1, 2);
        l0 = l0 * alpha0 + ps0;
        l1 = l1 * alpha1 + ps1;

#pragma unroll
        for (int nt = 0; nt < 8; nt++) {
            oacc[nt][0] *= alpha0; oacc[nt][1] *= alpha0;
            oacc[nt][2] *= alpha1; oacc[nt][3] *= alpha1;
        }

        // ---- P -> smem (reuse Ksh), C-frag layout -> A-frag layout --------
        __syncthreads();   // all warps done reading Ksh (K tile)
#pragma unroll
        for (int nt = 0; nt < 8; nt++) {
            const int c = nt * 8 + 2 * tig;
            *(uint2*)&Ksh[(mrow + g) * KST + c] =
                make_uint2(f2tf32(sacc[nt][0]), f2tf32(sacc[nt][1]));
            *(uint2*)&Ksh[(mrow + g + 8) * KST + c] =
                make_uint2(f2tf32(sacc[nt][2]), f2tf32(sacc[nt][3]));
        }
        __syncwarp();      // warp reads only its own P rows

        // ---- O += P V ------------------------------------------------------
#pragma unroll
        for (int ks = 0; ks < 8; ks++) {
            uint32_t pa0 = Ksh[(mrow + g) * KST + ks * 8 + tig];
            uint32_t pa1 = Ksh[(mrow + g + 8) * KST + ks * 8 + tig];
            uint32_t pa2 = Ksh[(mrow + g) * KST + ks * 8 + tig + 4];
            uint32_t pa3 = Ksh[(mrow + g + 8) * KST + ks * 8 + tig + 4];
#pragma unroll
            for (int nt = 0; nt < 8; nt++) {
                uint32_t b0 = Vsh[(ks * 8 + tig) * KST + nt * 8 + g];
                uint32_t b1 = Vsh[(ks * 8 + tig + 4) * KST + nt * 8 + g];
                mma_tf32(oacc[nt], pa0, pa1, pa2, pa3, b0, b1);
            }
        }
        __syncthreads();   // before next tile overwrites Ksh/Vsh
    }

    // ---- write partials ----------------------------------------------------
    const int unit = (b * 32 + qb) * 4 + chunk;
    const int lr0 = mrow + g;            // local rows within 64
    const int lr1 = lr0 + 8;
    if (tig == 0) {
        g_part_m[unit * 64 + lr0] = m0r;
        g_part_m[unit * 64 + lr1] = m1r;
        g_part_l[unit * 64 + lr0] = l0;
        g_part_l[unit * 64 + lr1] = l1;
    }
#pragma unroll
    for (int nt = 0; nt < 8; nt++) {
        const int c = nt * 8 + 2 * tig;
        *(float2*)&g_part_o[((size_t)(unit * 64 + lr0)) * HS + c] =
            make_float2(oacc[nt][0], oacc[nt][1]);
        *(float2*)&g_part_o[((size_t)(unit * 64 + lr1)) * HS + c] =
            make_float2(oacc[nt][2], oacc[nt][3]);
    }
}

// ---------------- combine split-K partials ---------------------------------
__global__ __launch_bounds__(128) void attn_combine(float* __restrict__ out) {
    const int row = blockIdx.x * 128 + threadIdx.x;   // 0..16383 (b*2048+t)
    const int b = row >> 11;
    const int t = row & 2047;
    const int qb = t >> 6;
    const int lane = t & 63;
    const int nchunk = (qb + 1 + 7) / 8;              // 1..4 active chunks
    const int base_unit = (b * 32 + qb) * 4;

    float M = -INFINITY;
    for (int c = 0; c < nchunk; c++)
        M = fmaxf(M, g_part_m[(base_unit + c) * 64 + lane]);

    float w[4];
    float L = 0.f;
    for (int c = 0; c < nchunk; c++) {
        float wm = __expf(g_part_m[(base_unit + c) * 64 + lane] - M);
        w[c] = wm;
        L += wm * g_part_l[(base_unit + c) * 64 + lane];
    }
    const float inv = 1.f / L;

    float* op = out + (size_t)row * HS;
#pragma unroll
    for (int i = 0; i < 16; i++) {
        float4 acc = make_float4(0.f, 0.f, 0.f, 0.f);
        for (int c = 0; c < nchunk; c++) {
            const float* po = g_part_o + ((size_t)((base_unit + c) * 64 + lane)) * HS;
            float4 v = *(const float4*)&po[i * 4];
            acc.x += w[c] * v.x; acc.y += w[c] * v.y;
            acc.z += w[c] * v.z; acc.w += w[c] * v.w;
        }
        acc.x *= inv; acc.y *= inv; acc.z *= inv; acc.w *= inv;
        *(float4*)&op[i * 4] = acc;
    }
}

// ---------------- launch ----------------------------------------------------
extern "C" void kernel_launch(void* const* d_in, const int* in_sizes, int n_in,
                              void* d_out, int out_size) {
    const float* x  = (const float*)d_in[0];
    const float* Wk = (const float*)d_in[1];
    const float* Wq = (const float*)d_in[2];
    const float* Wv = (const float*)d_in[3];
    float* out = (float*)d_out;

    qkv_gemm_tc<<<dim3(MROWS / 128, 3), 128>>>(x, Wk, Wq, Wv);
    attn_partial_tc<<<dim3(4, 32, BATCH), 128>>>();
    attn_combine<<<dim3(MROWS / 128), 128>>>(out);
}

// round 6
// speedup vs baseline: 3.2535x; 1.0158x over previous
#include <cuda_runtime.h>
#include <math.h>
#include <stdint.h>

#define TOK   2048
#define BATCH 8
#define NEMBD 768
#define HS    64
#define MROWS (BATCH*TOK)          // 16384

// ---------------- scratch (device globals; no allocation allowed) ----------
// q/k/v hold tf32-converted bits (q pre-scaled by 1/8)
static __device__ uint32_t g_q[MROWS*HS];
static __device__ uint32_t g_k[MROWS*HS];
static __device__ uint32_t g_v[MROWS*HS];

// split-K partials: unit = ((b*32 + qb)*4 + chunk), 1024 units x 64 rows
static __device__ float g_part_o[1024*64*HS];
static __device__ float g_part_m[1024*64];
static __device__ float g_part_l[1024*64];

// ---------------- tf32 helpers ---------------------------------------------
__device__ __forceinline__ uint32_t f2tf32(float f) {
    uint32_t u;
    asm("cvt.rna.tf32.f32 %0, %1;" : "=r"(u) : "f"(f));
    return u;
}

__device__ __forceinline__ void mma_tf32(float c[4],
                                         uint32_t a0, uint32_t a1, uint32_t a2, uint32_t a3,
                                         uint32_t b0, uint32_t b1) {
    asm volatile(
        "mma.sync.aligned.m16n8k8.row.col.f32.tf32.tf32.f32 "
        "{%0,%1,%2,%3},{%4,%5,%6,%7},{%8,%9},{%0,%1,%2,%3};"
        : "+f"(c[0]), "+f"(c[1]), "+f"(c[2]), "+f"(c[3])
        : "r"(a0), "r"(a1), "r"(a2), "r"(a3), "r"(b0), "r"(b1));
}

// ---------------- QKV projection: out[M,64] = x[M,768] @ W[768,64] ---------
// block = 128 threads (4 warps), tile 128 rows x 64 cols, BK = 32
// AST=36 (=4 mod 32, >=32 row width): A-frag bank = 4g+tig       -> conflict-free
// BST=72 (=8 mod 32, >=64 row width): B-frag bank = 8tig+g+const -> conflict-free
#define AST 36
#define BST 72
__global__ __launch_bounds__(128) void qkv_gemm_tc(const float* __restrict__ x,
                                                   const float* __restrict__ Wk,
                                                   const float* __restrict__ Wq,
                                                   const float* __restrict__ Wv) {
    __shared__ uint32_t As[128 * AST];
    __shared__ uint32_t Bs[32 * BST];

    const float* W;
    uint32_t* out;
    float oscale;
    if (blockIdx.y == 0)      { W = Wq; out = g_q; oscale = 0.125f; }
    else if (blockIdx.y == 1) { W = Wk; out = g_k; oscale = 1.0f; }
    else                      { W = Wv; out = g_v; oscale = 1.0f; }

    const int tid  = threadIdx.x;
    const int warp = tid >> 5;
    const int lane = tid & 31;
    const int g    = lane >> 2;
    const int tig  = lane & 3;
    const int row0 = blockIdx.x * 128;

    float acc[2][8][4];
#pragma unroll
    for (int mt = 0; mt < 2; mt++)
#pragma unroll
        for (int nt = 0; nt < 8; nt++)
#pragma unroll
            for (int i = 0; i < 4; i++) acc[mt][nt][i] = 0.f;

    for (int k0 = 0; k0 < NEMBD; k0 += 32) {
        // A tile 128x32 (coalesced: 8 lanes per row)
#pragma unroll
        for (int i = 0; i < 8; i++) {
            int idx = tid + i * 128;           // 0..1023 float4 slots
            int r   = idx >> 3;
            int c4  = (idx & 7) * 4;
            float4 a = *(const float4*)&x[(size_t)(row0 + r) * NEMBD + k0 + c4];
            uint4 t = make_uint4(f2tf32(a.x), f2tf32(a.y), f2tf32(a.z), f2tf32(a.w));
            *(uint4*)&As[r * AST + c4] = t;
        }
        // B tile 32x64
#pragma unroll
        for (int i = 0; i < 4; i++) {
            int idx = tid + i * 128;           // 0..511 float4 slots
            int r   = idx >> 4;
            int c4  = (idx & 15) * 4;
            float4 b = *(const float4*)&W[(size_t)(k0 + r) * HS + c4];
            uint4 t = make_uint4(f2tf32(b.x), f2tf32(b.y), f2tf32(b.z), f2tf32(b.w));
            *(uint4*)&Bs[r * BST + c4] = t;
        }
        __syncthreads();

#pragma unroll
        for (int kk = 0; kk < 4; kk++) {
            uint32_t af[2][4];
#pragma unroll
            for (int mt = 0; mt < 2; mt++) {
                const int m0 = warp * 32 + mt * 16;
                af[mt][0] = As[(m0 + g) * AST + kk * 8 + tig];
                af[mt][1] = As[(m0 + g + 8) * AST + kk * 8 + tig];
                af[mt][2] = As[(m0 + g) * AST + kk * 8 + tig + 4];
                af[mt][3] = As[(m0 + g + 8) * AST + kk * 8 + tig + 4];
            }
#pragma unroll
            for (int nt = 0; nt < 8; nt++) {
                uint32_t b0 = Bs[(kk * 8 + tig) * BST + nt * 8 + g];
                uint32_t b1 = Bs[(kk * 8 + tig + 4) * BST + nt * 8 + g];
                mma_tf32(acc[0][nt], af[0][0], af[0][1], af[0][2], af[0][3], b0, b1);
                mma_tf32(acc[1][nt], af[1][0], af[1][1], af[1][2], af[1][3], b0, b1);
            }
        }
        __syncthreads();
    }

    // epilogue: scale (Q only) + convert to tf32 bits
#pragma unroll
    for (int mt = 0; mt < 2; mt++) {
        const int r0 = row0 + warp * 32 + mt * 16 + g;
#pragma unroll
        for (int nt = 0; nt < 8; nt++) {
            const int c = nt * 8 + 2 * tig;
            *(uint2*)&out[(size_t)r0 * HS + c] =
                make_uint2(f2tf32(acc[mt][nt][0] * oscale), f2tf32(acc[mt][nt][1] * oscale));
            *(uint2*)&out[(size_t)(r0 + 8) * HS + c] =
                make_uint2(f2tf32(acc[mt][nt][2] * oscale), f2tf32(acc[mt][nt][3] * oscale));
        }
    }
}

// ---------------- flash attention partial (tensor cores, split along keys) --
// grid = (4 chunks, 32 qblocks, 8 batches), 128 threads (4 warps)
// block handles 64 q rows; warp w handles rows w*16 .. w*16+15
// Ksh stride 68 (=4 mod 32): K-frag rows indexed by nt*8+g -> bank 4g+tig, conflict-free
// Vsh stride 72 (=8 mod 32): V-frag rows indexed by ks*8+tig -> bank 8tig+g, conflict-free
#define KSTK 68
#define KSTV 72
__global__ __launch_bounds__(128) void attn_partial_tc() {
    __shared__ uint32_t Ksh[64 * KSTK];
    __shared__ uint32_t Vsh[64 * KSTV];

    const int chunk = blockIdx.x;
    const int qb    = blockIdx.y;        // 0..31, 64 rows each
    const int b     = blockIdx.z;

    const int nkb = qb + 1;              // 64-key tiles needed (causal)
    const int kb0 = chunk * 8;
    if (kb0 >= nkb) return;
    const int kb1 = (kb0 + 8 < nkb) ? kb0 + 8 : nkb;

    const int tid  = threadIdx.x;
    const int warp = tid >> 5;
    const int lane = tid & 31;
    const int g    = lane >> 2;
    const int tig  = lane & 3;
    const int qrow0 = qb * 64;           // block's first q row (within batch)

    // ---- stage Q (already tf32+scaled) through Vsh, pull fragments ---------
#pragma unroll
    for (int i = 0; i < 8; i++) {
        int idx = tid + i * 128;
        int r   = idx >> 4;
        int c4  = (idx & 15) * 4;
        *(uint4*)&Vsh[r * KSTV + c4] =
            *(const uint4*)&g_q[((size_t)(b * TOK + qrow0 + r)) * HS + c4];
    }
    __syncthreads();

    uint32_t qf[8][4];
    const int mrow = warp * 16;          // warp's first local row
#pragma unroll
    for (int ks = 0; ks < 8; ks++) {
        qf[ks][0] = Vsh[(mrow + g) * KSTV + ks * 8 + tig];
        qf[ks][1] = Vsh[(mrow + g + 8) * KSTV + ks * 8 + tig];
        qf[ks][2] = Vsh[(mrow + g) * KSTV + ks * 8 + tig + 4];
        qf[ks][3] = Vsh[(mrow + g + 8) * KSTV + ks * 8 + tig + 4];
    }
    __syncthreads();

    float oacc[8][4];
#pragma unroll
    for (int nt = 0; nt < 8; nt++)
#pragma unroll
        for (int i = 0; i < 4; i++) oacc[nt][i] = 0.f;

    float m0r = -INFINITY, m1r = -INFINITY;   // rows g and g+8
    float l0 = 0.f, l1 = 0.f;

    const int rg0 = qrow0 + mrow + g;         // global (in-batch) q rows
    const int rg1 = rg0 + 8;

    // shuffle sources for C-frag -> A-frag redistribution
    const int src0 = (lane & ~3) | (tig >> 1);
    const int src1 = src0 + 2;
    const bool odd = (tig & 1);

    for (int kb = kb0; kb < kb1; kb++) {
        // ---- load K and V tiles (pure uint4 copies, already tf32) ---------
#pragma unroll
        for (int i = 0; i < 8; i++) {
            int idx = tid + i * 128;
            int r   = idx >> 4;
            int c4  = (idx & 15) * 4;
            size_t base = ((size_t)(b * TOK + kb * 64 + r)) * HS + c4;
            *(uint4*)&Ksh[r * KSTK + c4] = *(const uint4*)&g_k[base];
            *(uint4*)&Vsh[r * KSTV + c4] = *(const uint4*)&g_v[base];
        }
        __syncthreads();

        // ---- S = Q K^T (16 x 64 per warp) ---------------------------------
        float sacc[8][4];
#pragma unroll
        for (int nt = 0; nt < 8; nt++) {
#pragma unroll
            for (int i = 0; i < 4; i++) sacc[nt][i] = 0.f;
#pragma unroll
            for (int ks = 0; ks < 8; ks++) {
                uint32_t b0 = Ksh[(nt * 8 + g) * KSTK + ks * 8 + tig];
                uint32_t b1 = Ksh[(nt * 8 + g) * KSTK + ks * 8 + tig + 4];
                mma_tf32(sacc[nt], qf[ks][0], qf[ks][1], qf[ks][2], qf[ks][3], b0, b1);
            }
        }

        // ---- causal mask (only the diagonal tile can clip) ----------------
        if (kb == qb) {
            const int colbase = kb * 64;
#pragma unroll
            for (int nt = 0; nt < 8; nt++) {
                const int c0 = colbase + nt * 8 + 2 * tig;
                if (c0 > rg0)     sacc[nt][0] = -INFINITY;
                if (c0 + 1 > rg0) sacc[nt][1] = -INFINITY;
                if (c0 > rg1)     sacc[nt][2] = -INFINITY;
                if (c0 + 1 > rg1) sacc[nt][3] = -INFINITY;
            }
        }

        // ---- online softmax -----------------------------------------------
        float mx0 = -INFINITY, mx1 = -INFINITY;
#pragma unroll
        for (int nt = 0; nt < 8; nt++) {
            mx0 = fmaxf(mx0, fmaxf(sacc[nt][0], sacc[nt][1]));
            mx1 = fmaxf(mx1, fmaxf(sacc[nt][2], sacc[nt][3]));
        }
        mx0 = fmaxf(mx0, __shfl_xor_sync(0xffffffffu, mx0, 1));
        mx0 = fmaxf(mx0, __shfl_xor_sync(0xffffffffu, mx0, 2));
        mx1 = fmaxf(mx1, __shfl_xor_sync(0xffffffffu, mx1, 1));
        mx1 = fmaxf(mx1, __shfl_xor_sync(0xffffffffu, mx1, 2));

        const float mn0 = fmaxf(m0r, mx0);
        const float mn1 = fmaxf(m1r, mx1);
        const float alpha0 = __expf(m0r - mn0);   // first iter: exp(-inf)=0
        const float alpha1 = __expf(m1r - mn1);
        m0r = mn0; m1r = mn1;

        float ps0 = 0.f, ps1 = 0.f;
#pragma unroll
        for (int nt = 0; nt < 8; nt++) {
            sacc[nt][0] = __expf(sacc[nt][0] - mn0);
            sacc[nt][1] = __expf(sacc[nt][1] - mn0);
            sacc[nt][2] = __expf(sacc[nt][2] - mn1);
            sacc[nt][3] = __expf(sacc[nt][3] - mn1);
            ps0 += sacc[nt][0] + sacc[nt][1];
            ps1 += sacc[nt][2] + sacc[nt][3];
        }
        ps0 += __shfl_xor_sync(0xffffffffu, ps0, 1);
        ps0 += __shfl_xor_sync(0xffffffffu, ps0, 2);
        ps1 += __shfl_xor_sync(0xffffffffu, ps1, 1);
        ps1 += __shfl_xor_sync(0xffffffffu, ps1, 2);
        l0 = l0 * alpha0 + ps0;
        l1 = l1 * alpha1 + ps1;

#pragma unroll
        for (int nt = 0; nt < 8; nt++) {
            oacc[nt][0] *= alpha0; oacc[nt][1] *= alpha0;
            oacc[nt][2] *= alpha1; oacc[nt][3] *= alpha1;
        }

        // ---- O += P V : P redistributed C-frag -> A-frag via shuffles ------
#pragma unroll
        for (int ks = 0; ks < 8; ks++) {
            const float p0a = __shfl_sync(0xffffffffu, sacc[ks][0], src0);
            const float p1a = __shfl_sync(0xffffffffu, sacc[ks][1], src0);
            const float p2a = __shfl_sync(0xffffffffu, sacc[ks][2], src0);
            const float p3a = __shfl_sync(0xffffffffu, sacc[ks][3], src0);
            const float p0b = __shfl_sync(0xffffffffu, sacc[ks][0], src1);
            const float p1b = __shfl_sync(0xffffffffu, sacc[ks][1], src1);
            const float p2b = __shfl_sync(0xffffffffu, sacc[ks][2], src1);
            const float p3b = __shfl_sync(0xffffffffu, sacc[ks][3], src1);
            const uint32_t pa0 = f2tf32(odd ? p1a : p0a);
            const uint32_t pa1 = f2tf32(odd ? p3a : p2a);
            const uint32_t pa2 = f2tf32(odd ? p1b : p0b);
            const uint32_t pa3 = f2tf32(odd ? p3b : p2b);
#pragma unroll
            for (int nt = 0; nt < 8; nt++) {
                uint32_t b0 = Vsh[(ks * 8 + tig) * KSTV + nt * 8 + g];
                uint32_t b1 = Vsh[(ks * 8 + tig + 4) * KSTV + nt * 8 + g];
                mma_tf32(oacc[nt], pa0, pa1, pa2, pa3, b0, b1);
            }
        }
        __syncthreads();   // before next tile overwrites Ksh/Vsh
    }

    // ---- write partials ----------------------------------------------------
    const int unit = (b * 32 + qb) * 4 + chunk;
    const int lr0 = mrow + g;            // local rows within 64
    const int lr1 = lr0 + 8;
    if (tig == 0) {
        g_part_m[unit * 64 + lr0] = m0r;
        g_part_m[unit * 64 + lr1] = m1r;
        g_part_l[unit * 64 + lr0] = l0;
        g_part_l[unit * 64 + lr1] = l1;
    }
#pragma unroll
    for (int nt = 0; nt < 8; nt++) {
        const int c = nt * 8 + 2 * tig;
        *(float2*)&g_part_o[((size_t)(unit * 64 + lr0)) * HS + c] =
            make_float2(oacc[nt][0], oacc[nt][1]);
        *(float2*)&g_part_o[((size_t)(unit * 64 + lr1)) * HS + c] =
            make_float2(oacc[nt][2], oacc[nt][3]);
    }
}

// ---------------- combine split-K partials ---------------------------------
__global__ __launch_bounds__(128) void attn_combine(float* __restrict__ out) {
    const int row = blockIdx.x * 128 + threadIdx.x;   // 0..16383 (b*2048+t)
    const int b = row >> 11;
    const int t = row & 2047;
    const int qb = t >> 6;
    const int lane = t & 63;
    const int nchunk = (qb + 1 + 7) / 8;              // 1..4 active chunks
    const int base_unit = (b * 32 + qb) * 4;

    float M = -INFINITY;
    for (int c = 0; c < nchunk; c++)
        M = fmaxf(M, g_part_m[(base_unit + c) * 64 + lane]);

    float w[4];
    float L = 0.f;
    for (int c = 0; c < nchunk; c++) {
        float wm = __expf(g_part_m[(base_unit + c) * 64 + lane] - M);
        w[c] = wm;
        L += wm * g_part_l[(base_unit + c) * 64 + lane];
    }
    const float inv = 1.f / L;

    float* op = out + (size_t)row * HS;
#pragma unroll
    for (int i = 0; i < 16; i++) {
        float4 acc = make_float4(0.f, 0.f, 0.f, 0.f);
        for (int c = 0; c < nchunk; c++) {
            const float* po = g_part_o + ((size_t)((base_unit + c) * 64 + lane)) * HS;
            float4 v = *(const float4*)&po[i * 4];
            acc.x += w[c] * v.x; acc.y += w[c] * v.y;
            acc.z += w[c] * v.z; acc.w += w[c] * v.w;
        }
        acc.x *= inv; acc.y *= inv; acc.z *= inv; acc.w *= inv;
        *(float4*)&op[i * 4] = acc;
    }
}

// ---------------- launch ----------------------------------------------------
extern "C" void kernel_launch(void* const* d_in, const int* in_sizes, int n_in,
                              void* d_out, int out_size) {
    const float* x  = (const float*)d_in[0];
    const float* Wk = (const float*)d_in[1];
    const float* Wq = (const float*)d_in[2];
    const float* Wv = (const float*)d_in[3];
    float* out = (float*)d_out;

    qkv_gemm_tc<<<dim3(MROWS / 128, 3), 128>>>(x, Wk, Wq, Wv);
    attn_partial_tc<<<dim3(4, 32, BATCH), 128>>>();
    attn_combine<<<dim3(MROWS / 128), 128>>>(out);
}

// round 7
// speedup vs baseline: 3.3425x; 1.0274x over previous
#include <cuda_runtime.h>
#include <math.h>
#include <stdint.h>

#define TOK   2048
#define BATCH 8
#define NEMBD 768
#define HS    64
#define MROWS (BATCH*TOK)          // 16384

// ---------------- scratch (device globals; no allocation allowed) ----------
// q/k/v hold tf32-converted bits (q pre-scaled by 1/8)
static __device__ uint32_t g_q[MROWS*HS];
static __device__ uint32_t g_k[MROWS*HS];
static __device__ uint32_t g_v[MROWS*HS];

// split-K partials: unit = ((b*32 + qb)*4 + chunk), 1024 units x 64 rows
static __device__ float g_part_o[1024*64*HS];
static __device__ float g_part_m[1024*64];
static __device__ float g_part_l[1024*64];

// ---------------- helpers ---------------------------------------------------
__device__ __forceinline__ uint32_t f2tf32(float f) {
    uint32_t u;
    asm("cvt.rna.tf32.f32 %0, %1;" : "=r"(u) : "f"(f));
    return u;
}
__device__ __forceinline__ uint32_t u2tf32(uint32_t bits) {
    return f2tf32(__uint_as_float(bits));
}

__device__ __forceinline__ void mma_tf32(float c[4],
                                         uint32_t a0, uint32_t a1, uint32_t a2, uint32_t a3,
                                         uint32_t b0, uint32_t b1) {
    asm volatile(
        "mma.sync.aligned.m16n8k8.row.col.f32.tf32.tf32.f32 "
        "{%0,%1,%2,%3},{%4,%5,%6,%7},{%8,%9},{%0,%1,%2,%3};"
        : "+f"(c[0]), "+f"(c[1]), "+f"(c[2]), "+f"(c[3])
        : "r"(a0), "r"(a1), "r"(a2), "r"(a3), "r"(b0), "r"(b1));
}

__device__ __forceinline__ void cp_async16(uint32_t dst_smem, const void* src) {
    asm volatile("cp.async.cg.shared.global [%0], [%1], 16;"
                 :: "r"(dst_smem), "l"(src));
}
__device__ __forceinline__ uint32_t smem_u32(const void* p) {
    return (uint32_t)__cvta_generic_to_shared(p);
}

// ---------------- QKV projection: out[M,64] = x[M,768] @ W[768,64] ---------
// block = 128 threads (4 warps), tile 128 rows x 64 cols, BK = 16, 3-stage cp.async
// ASTQ=20 (=4 mod 32, >=16): A-frag bank = perm4(g)+tig     -> conflict-free
// BSTQ=72 (=8 mod 32, >=64): B-frag bank = 8tig+g+const     -> conflict-free
#define ASTQ 20
#define BSTQ 72
#define KT   48    // 768/16 BK-iterations
__global__ __launch_bounds__(128) void qkv_gemm_tc(const float* __restrict__ x,
                                                   const float* __restrict__ Wk,
                                                   const float* __restrict__ Wq,
                                                   const float* __restrict__ Wv) {
    __shared__ uint32_t As[3][128 * ASTQ];   // raw fp32 bits
    __shared__ uint32_t Bs[3][16 * BSTQ];

    const float* W;
    uint32_t* out;
    float oscale;
    if (blockIdx.y == 0)      { W = Wq; out = g_q; oscale = 0.125f; }
    else if (blockIdx.y == 1) { W = Wk; out = g_k; oscale = 1.0f; }
    else                      { W = Wv; out = g_v; oscale = 1.0f; }

    const int tid  = threadIdx.x;
    const int warp = tid >> 5;
    const int lane = tid & 31;
    const int g    = lane >> 2;
    const int tig  = lane & 3;
    const int row0 = blockIdx.x * 128;

    // per-thread cp.async source/dest precompute
    // A: 4 x 16B per thread: idx = tid + i*128; r = idx>>2 (0..127), c4 = (idx&3)*4
    // B: 2 x 16B per thread: idx = tid + i*128; r = idx>>4 (0..15),  c4 = (idx&15)*4
    const int ar = tid >> 2;            // row handled for i=0 (rows ar, ar+32, ...)
    const int ac = (tid & 3) * 4;
    const int br = tid >> 4;
    const int bc = (tid & 15) * 4;

    float acc[2][8][4];
#pragma unroll
    for (int mt = 0; mt < 2; mt++)
#pragma unroll
        for (int nt = 0; nt < 8; nt++)
#pragma unroll
            for (int i = 0; i < 4; i++) acc[mt][nt][i] = 0.f;

#define QKV_ISSUE(s, k0)                                                          \
    do {                                                                          \
        _Pragma("unroll")                                                         \
        for (int i = 0; i < 4; i++) {                                             \
            int r = ar + i * 32;                                                  \
            cp_async16(smem_u32(&As[s][r * ASTQ + ac]),                           \
                       &x[(size_t)(row0 + r) * NEMBD + (k0) + ac]);               \
        }                                                                         \
        _Pragma("unroll")                                                         \
        for (int i = 0; i < 2; i++) {                                             \
            int r = br + i * 8;                                                   \
            cp_async16(smem_u32(&Bs[s][r * BSTQ + bc]),                           \
                       &W[(size_t)((k0) + r) * HS + bc]);                         \
        }                                                                         \
        asm volatile("cp.async.commit_group;");                                   \
    } while (0)

    QKV_ISSUE(0, 0);
    QKV_ISSUE(1, 16);

    for (int it = 0; it < KT; it++) {
        if (it == KT - 1) asm volatile("cp.async.wait_group 0;");
        else              asm volatile("cp.async.wait_group 1;");
        __syncthreads();

        if (it + 2 < KT) QKV_ISSUE((it + 2) % 3, (it + 2) * 16);

        const uint32_t* as = As[it % 3];
        const uint32_t* bs = Bs[it % 3];

#pragma unroll
        for (int kk = 0; kk < 2; kk++) {
            uint32_t af[2][4];
#pragma unroll
            for (int mt = 0; mt < 2; mt++) {
                const int m0 = warp * 32 + mt * 16;
                af[mt][0] = u2tf32(as[(m0 + g) * ASTQ + kk * 8 + tig]);
                af[mt][1] = u2tf32(as[(m0 + g + 8) * ASTQ + kk * 8 + tig]);
                af[mt][2] = u2tf32(as[(m0 + g) * ASTQ + kk * 8 + tig + 4]);
                af[mt][3] = u2tf32(as[(m0 + g + 8) * ASTQ + kk * 8 + tig + 4]);
            }
#pragma unroll
            for (int nt = 0; nt < 8; nt++) {
                uint32_t b0 = u2tf32(bs[(kk * 8 + tig) * BSTQ + nt * 8 + g]);
                uint32_t b1 = u2tf32(bs[(kk * 8 + tig + 4) * BSTQ + nt * 8 + g]);
                mma_tf32(acc[0][nt], af[0][0], af[0][1], af[0][2], af[0][3], b0, b1);
                mma_tf32(acc[1][nt], af[1][0], af[1][1], af[1][2], af[1][3], b0, b1);
            }
        }
        // no trailing sync needed: next iteration's wait+sync protects buffers
    }

    // epilogue: scale (Q only) + convert to tf32 bits
#pragma unroll
    for (int mt = 0; mt < 2; mt++) {
        const int r0 = row0 + warp * 32 + mt * 16 + g;
#pragma unroll
        for (int nt = 0; nt < 8; nt++) {
            const int c = nt * 8 + 2 * tig;
            *(uint2*)&out[(size_t)r0 * HS + c] =
                make_uint2(f2tf32(acc[mt][nt][0] * oscale), f2tf32(acc[mt][nt][1] * oscale));
            *(uint2*)&out[(size_t)(r0 + 8) * HS + c] =
                make_uint2(f2tf32(acc[mt][nt][2] * oscale), f2tf32(acc[mt][nt][3] * oscale));
        }
    }
}

// ---------------- flash attention partial (tensor cores, split along keys) --
// grid = (4 chunks, 32 qblocks, 8 batches), 128 threads (4 warps)
// block handles 64 q rows; warp w handles rows w*16 .. w*16+15
// Ksh stride 68 (=4 mod 32): K-frag rows indexed by nt*8+g -> bank 4g+tig, conflict-free
// Vsh stride 72 (=8 mod 32): V-frag rows indexed by ks*8+tig -> bank 8tig+g, conflict-free
#define KSTK 68
#define KSTV 72
__global__ __launch_bounds__(128) void attn_partial_tc() {
    __shared__ uint32_t Ksh[64 * KSTK];
    __shared__ uint32_t Vsh[64 * KSTV];

    const int chunk = blockIdx.x;
    const int qb    = blockIdx.y;        // 0..31, 64 rows each
    const int b     = blockIdx.z;

    const int nkb = qb + 1;              // 64-key tiles needed (causal)
    const int kb0 = chunk * 8;
    if (kb0 >= nkb) return;
    const int kb1 = (kb0 + 8 < nkb) ? kb0 + 8 : nkb;

    const int tid  = threadIdx.x;
    const int warp = tid >> 5;
    const int lane = tid & 31;
    const int g    = lane >> 2;
    const int tig  = lane & 3;
    const int qrow0 = qb * 64;           // block's first q row (within batch)

    // ---- stage Q (already tf32+scaled) through Vsh, pull fragments ---------
#pragma unroll
    for (int i = 0; i < 8; i++) {
        int idx = tid + i * 128;
        int r   = idx >> 4;
        int c4  = (idx & 15) * 4;
        *(uint4*)&Vsh[r * KSTV + c4] =
            *(const uint4*)&g_q[((size_t)(b * TOK + qrow0 + r)) * HS + c4];
    }
    __syncthreads();

    uint32_t qf[8][4];
    const int mrow = warp * 16;          // warp's first local row
#pragma unroll
    for (int ks = 0; ks < 8; ks++) {
        qf[ks][0] = Vsh[(mrow + g) * KSTV + ks * 8 + tig];
        qf[ks][1] = Vsh[(mrow + g + 8) * KSTV + ks * 8 + tig];
        qf[ks][2] = Vsh[(mrow + g) * KSTV + ks * 8 + tig + 4];
        qf[ks][3] = Vsh[(mrow + g + 8) * KSTV + ks * 8 + tig + 4];
    }
    __syncthreads();

    float oacc[8][4];
#pragma unroll
    for (int nt = 0; nt < 8; nt++)
#pragma unroll
        for (int i = 0; i < 4; i++) oacc[nt][i] = 0.f;

    float m0r = -INFINITY, m1r = -INFINITY;   // rows g and g+8
    float l0 = 0.f, l1 = 0.f;

    const int rg0 = qrow0 + mrow + g;         // global (in-batch) q rows
    const int rg1 = rg0 + 8;

    // shuffle sources for C-frag -> A-frag redistribution
    const int src0 = (lane & ~3) | (tig >> 1);
    const int src1 = src0 + 2;
    const bool odd = (tig & 1);

    for (int kb = kb0; kb < kb1; kb++) {
        // ---- load K and V tiles (pure uint4 copies, already tf32) ---------
#pragma unroll
        for (int i = 0; i < 8; i++) {
            int idx = tid + i * 128;
            int r   = idx >> 4;
            int c4  = (idx & 15) * 4;
            size_t base = ((size_t)(b * TOK + kb * 64 + r)) * HS + c4;
            *(uint4*)&Ksh[r * KSTK + c4] = *(const uint4*)&g_k[base];
            *(uint4*)&Vsh[r * KSTV + c4] = *(const uint4*)&g_v[base];
        }
        __syncthreads();

        // ---- S = Q K^T (16 x 64 per warp) ---------------------------------
        float sacc[8][4];
#pragma unroll
        for (int nt = 0; nt < 8; nt++) {
#pragma unroll
            for (int i = 0; i < 4; i++) sacc[nt][i] = 0.f;
#pragma unroll
            for (int ks = 0; ks < 8; ks++) {
                uint32_t b0 = Ksh[(nt * 8 + g) * KSTK + ks * 8 + tig];
                uint32_t b1 = Ksh[(nt * 8 + g) * KSTK + ks * 8 + tig + 4];
                mma_tf32(sacc[nt], qf[ks][0], qf[ks][1], qf[ks][2], qf[ks][3], b0, b1);
            }
        }

        // ---- causal mask (only the diagonal tile can clip) ----------------
        if (kb == qb) {
            const int colbase = kb * 64;
#pragma unroll
            for (int nt = 0; nt < 8; nt++) {
                const int c0 = colbase + nt * 8 + 2 * tig;
                if (c0 > rg0)     sacc[nt][0] = -INFINITY;
                if (c0 + 1 > rg0) sacc[nt][1] = -INFINITY;
                if (c0 > rg1)     sacc[nt][2] = -INFINITY;
                if (c0 + 1 > rg1) sacc[nt][3] = -INFINITY;
            }
        }

        // ---- online softmax -----------------------------------------------
        float mx0 = -INFINITY, mx1 = -INFINITY;
#pragma unroll
        for (int nt = 0; nt < 8; nt++) {
            mx0 = fmaxf(mx0, fmaxf(sacc[nt][0], sacc[nt][1]));
            mx1 = fmaxf(mx1, fmaxf(sacc[nt][2], sacc[nt][3]));
        }
        mx0 = fmaxf(mx0, __shfl_xor_sync(0xffffffffu, mx0, 1));
        mx0 = fmaxf(mx0, __shfl_xor_sync(0xffffffffu, mx0, 2));
        mx1 = fmaxf(mx1, __shfl_xor_sync(0xffffffffu, mx1, 1));
        mx1 = fmaxf(mx1, __shfl_xor_sync(0xffffffffu, mx1, 2));

        const float mn0 = fmaxf(m0r, mx0);
        const float mn1 = fmaxf(m1r, mx1);
        const float alpha0 = __expf(m0r - mn0);   // first iter: exp(-inf)=0
        const float alpha1 = __expf(m1r - mn1);
        m0r = mn0; m1r = mn1;

        float ps0 = 0.f, ps1 = 0.f;
#pragma unroll
        for (int nt = 0; nt < 8; nt++) {
            sacc[nt][0] = __expf(sacc[nt][0] - mn0);
            sacc[nt][1] = __expf(sacc[nt][1] - mn0);
            sacc[nt][2] = __expf(sacc[nt][2] - mn1);
            sacc[nt][3] = __expf(sacc[nt][3] - mn1);
            ps0 += sacc[nt][0] + sacc[nt][1];
            ps1 += sacc[nt][2] + sacc[nt][3];
        }
        ps0 += __shfl_xor_sync(0xffffffffu, ps0, 1);
        ps0 += __shfl_xor_sync(0xffffffffu, ps0, 2);
        ps1 += __shfl_xor_sync(0xffffffffu, ps1, 1);
        ps1 += __shfl_xor_sync(0xffffffffu, ps1, 2);
        l0 = l0 * alpha0 + ps0;
        l1 = l1 * alpha1 + ps1;

#pragma unroll
        for (int nt = 0; nt < 8; nt++) {
            oacc[nt][0] *= alpha0; oacc[nt][1] *= alpha0;
            oacc[nt][2] *= alpha1; oacc[nt][3] *= alpha1;
        }

        // ---- O += P V : P redistributed C-frag -> A-frag via shuffles ------
#pragma unroll
        for (int ks = 0; ks < 8; ks++) {
            const float p0a = __shfl_sync(0xffffffffu, sacc[ks][0], src0);
            const float p1a = __shfl_sync(0xffffffffu, sacc[ks][1], src0);
            const float p2a = __shfl_sync(0xffffffffu, sacc[ks][2], src0);
            const float p3a = __shfl_sync(0xffffffffu, sacc[ks][3], src0);
            const float p0b = __shfl_sync(0xffffffffu, sacc[ks][0], src1);
            const float p1b = __shfl_sync(0xffffffffu, sacc[ks][1], src1);
            const float p2b = __shfl_sync(0xffffffffu, sacc[ks][2], src1);
            const float p3b = __shfl_sync(0xffffffffu, sacc[ks][3], src1);
            const uint32_t pa0 = f2tf32(odd ? p1a : p0a);
            const uint32_t pa1 = f2tf32(odd ? p3a : p2a);
            const uint32_t pa2 = f2tf32(odd ? p1b : p0b);
            const uint32_t pa3 = f2tf32(odd ? p3b : p2b);
#pragma unroll
            for (int nt = 0; nt < 8; nt++) {
                uint32_t b0 = Vsh[(ks * 8 + tig) * KSTV + nt * 8 + g];
                uint32_t b1 = Vsh[(ks * 8 + tig + 4) * KSTV + nt * 8 + g];
                mma_tf32(oacc[nt], pa0, pa1, pa2, pa3, b0, b1);
            }
        }
        __syncthreads();   // before next tile overwrites Ksh/Vsh
    }

    // ---- write partials ----------------------------------------------------
    const int unit = (b * 32 + qb) * 4 + chunk;
    const int lr0 = mrow + g;            // local rows within 64
    const int lr1 = lr0 + 8;
    if (tig == 0) {
        g_part_m[unit * 64 + lr0] = m0r;
        g_part_m[unit * 64 + lr1] = m1r;
        g_part_l[unit * 64 + lr0] = l0;
        g_part_l[unit * 64 + lr1] = l1;
    }
#pragma unroll
    for (int nt = 0; nt < 8; nt++) {
        const int c = nt * 8 + 2 * tig;
        *(float2*)&g_part_o[((size_t)(unit * 64 + lr0)) * HS + c] =
            make_float2(oacc[nt][0], oacc[nt][1]);
        *(float2*)&g_part_o[((size_t)(unit * 64 + lr1)) * HS + c] =
            make_float2(oacc[nt][2], oacc[nt][3]);
    }
}

// ---------------- combine split-K partials ---------------------------------
__global__ __launch_bounds__(128) void attn_combine(float* __restrict__ out) {
    const int row = blockIdx.x * 128 + threadIdx.x;   // 0..16383 (b*2048+t)
    const int b = row >> 11;
    const int t = row & 2047;
    const int qb = t >> 6;
    const int lane = t & 63;
    const int nchunk = (qb + 1 + 7) / 8;              // 1..4 active chunks
    const int base_unit = (b * 32 + qb) * 4;

    float M = -INFINITY;
    for (int c = 0; c < nchunk; c++)
        M = fmaxf(M, g_part_m[(base_unit + c) * 64 + lane]);

    float w[4];
    float L = 0.f;
    for (int c = 0; c < nchunk; c++) {
        float wm = __expf(g_part_m[(base_unit + c) * 64 + lane] - M);
        w[c] = wm;
        L += wm * g_part_l[(base_unit + c) * 64 + lane];
    }
    const float inv = 1.f / L;

    float* op = out + (size_t)row * HS;
#pragma unroll
    for (int i = 0; i < 16; i++) {
        float4 acc = make_float4(0.f, 0.f, 0.f, 0.f);
        for (int c = 0; c < nchunk; c++) {
            const float* po = g_part_o + ((size_t)((base_unit + c) * 64 + lane)) * HS;
            float4 v = *(const float4*)&po[i * 4];
            acc.x += w[c] * v.x; acc.y += w[c] * v.y;
            acc.z += w[c] * v.z; acc.w += w[c] * v.w;
        }
        acc.x *= inv; acc.y *= inv; acc.z *= inv; acc.w *= inv;
        *(float4*)&op[i * 4] = acc;
    }
}

// ---------------- launch ----------------------------------------------------
extern "C" void kernel_launch(void* const* d_in, const int* in_sizes, int n_in,
                              void* d_out, int out_size) {
    const float* x  = (const float*)d_in[0];
    const float* Wk = (const float*)d_in[1];
    const float* Wq = (const float*)d_in[2];
    const float* Wv = (const float*)d_in[3];
    float* out = (float*)d_out;

    qkv_gemm_tc<<<dim3(MROWS / 128, 3), 128>>>(x, Wk, Wq, Wv);
    attn_partial_tc<<<dim3(4, 32, BATCH), 128>>>();
    attn_combine<<<dim3(MROWS / 128), 128>>>(out);
}